// round 4
// baseline (speedup 1.0000x reference)
#include <cuda_runtime.h>
#include <cuda_bf16.h>

#define D_MODEL 1024
#define N_LEVELS 8
#define TPB 256
#define COLS 4                 // columns per thread (float4)
#define NWARP (TPB / 32)       // 8 warps
#define HALF_L 3.9960f         // 8 * (1 - 1e-3) / 2
#define LN_EPS 1e-5f
#define INV_D (1.0f / 1024.0f)

__global__ __launch_bounds__(TPB) void fsq_kernel(
    const float* __restrict__ x,     // [rows, 1024]
    const float* __restrict__ ln_w,  // [1024]
    const float* __restrict__ ln_b,  // [1024]
    const float* __restrict__ W,     // [8, 1024]
    float* __restrict__ out,         // [rows, 8]
    int rows)
{
    __shared__ float red[2][NWARP][16];  // double-buffered reduce scratch
    __shared__ float sG[N_LEVELS];       // sum_d ln_w[d]*W[n,d]
    __shared__ float sC[N_LEVELS];       // sum_d ln_b[d]*W[n,d]

    const int t    = threadIdx.x;
    const int warp = t >> 5;
    const int lane = t & 31;
    const int base = t * COLS;           // this thread's columns [base, base+4)

    // ---- Load per-thread weights into registers (once per block) ----
    float lw[COLS], lb[COLS];
    float g[N_LEVELS][COLS];
    #pragma unroll
    for (int j = 0; j < COLS; j++) {
        lw[j] = ln_w[base + j];
        lb[j] = ln_b[base + j];
    }
    float pG[N_LEVELS], pC[N_LEVELS];
    #pragma unroll
    for (int n = 0; n < N_LEVELS; n++) {
        float sg = 0.f, sc = 0.f;
        #pragma unroll
        for (int j = 0; j < COLS; j++) {
            float w = W[n * D_MODEL + base + j];
            g[n][j] = lw[j] * w;
            sg += g[n][j];
            sc = fmaf(lb[j], w, sc);
        }
        pG[n] = sg;
        pC[n] = sc;
    }

    // ---- Block-reduce pG/pC (16 values), once per block ----
    {
        float v[16];
        #pragma unroll
        for (int n = 0; n < N_LEVELS; n++) { v[n] = pG[n]; v[8 + n] = pC[n]; }
        #pragma unroll
        for (int off = 16; off > 0; off >>= 1) {
            #pragma unroll
            for (int k = 0; k < 16; k++)
                v[k] += __shfl_xor_sync(0xFFFFFFFFu, v[k], off);
        }
        if (lane == 0) {
            #pragma unroll
            for (int k = 0; k < 16; k++) red[0][warp][k] = v[k];
        }
        __syncthreads();
        if (t < 16) {
            float s = 0.f;
            #pragma unroll
            for (int w = 0; w < NWARP; w++) s += red[0][w][t];
            if (t < 8) sG[t] = s; else sC[t - 8] = s;
        }
        __syncthreads();
    }

    // ---- Main persistent loop over rows ----
    int parity = 0;
    for (int row = blockIdx.x; row < rows; row += gridDim.x) {
        const float4 xv =
            reinterpret_cast<const float4*>(x + (size_t)row * D_MODEL)[t];
        float xj[COLS] = {xv.x, xv.y, xv.z, xv.w};

        // 10 partial accumulators: [0]=sum, [1]=sumsq, [2..9]=dots
        float v[10];
        {
            float s = 0.f, sq = 0.f;
            #pragma unroll
            for (int j = 0; j < COLS; j++) {
                s += xj[j];
                sq = fmaf(xj[j], xj[j], sq);
            }
            v[0] = s; v[1] = sq;
            #pragma unroll
            for (int n = 0; n < N_LEVELS; n++) {
                float d = 0.f;
                #pragma unroll
                for (int j = 0; j < COLS; j++) d = fmaf(g[n][j], xj[j], d);
                v[2 + n] = d;
            }
        }

        // warp reduce 10 values
        #pragma unroll
        for (int off = 16; off > 0; off >>= 1) {
            #pragma unroll
            for (int k = 0; k < 10; k++)
                v[k] += __shfl_xor_sync(0xFFFFFFFFu, v[k], off);
        }
        if (lane == 0) {
            #pragma unroll
            for (int k = 0; k < 10; k++) red[parity][warp][k] = v[k];
        }
        __syncthreads();

        if (t < N_LEVELS) {
            float sum = 0.f, sumsq = 0.f, dt = 0.f;
            #pragma unroll
            for (int w = 0; w < NWARP; w++) {
                sum   += red[parity][w][0];
                sumsq += red[parity][w][1];
                dt    += red[parity][w][2 + t];
            }
            float mean = sum * INV_D;
            float var  = fmaf(sumsq, INV_D, -mean * mean);
            float rstd = rsqrtf(var + LN_EPS);
            float z    = fmaf(rstd, fmaf(-mean, sG[t], dt), sC[t]);
            float bounded = HALF_L * tanhf(z);
            out[(size_t)row * N_LEVELS + t] = rintf(bounded);  // round half-to-even
        }
        parity ^= 1;
        // double buffering: next iteration writes the other buffer; the
        // __syncthreads inside the next iteration orders reuse of this one.
    }
}

extern "C" void kernel_launch(void* const* d_in, const int* in_sizes, int n_in,
                              void* d_out, int out_size) {
    const float* regrs = (const float*)d_in[0];
    const float* ln_w  = (const float*)d_in[1];
    const float* ln_b  = (const float*)d_in[2];
    const float* W     = (const float*)d_in[3];
    float* out = (float*)d_out;

    int rows = in_sizes[0] / D_MODEL;  // 32768
    int grid = 148 * 8;                // persistent: 8 blocks/SM on 148 SMs
    if (grid > rows) grid = rows;

    fsq_kernel<<<grid, TPB>>>(regrs, ln_w, ln_b, W, out, rows);
}